// round 16
// baseline (speedup 1.0000x reference)
#include <cuda_runtime.h>
#include <math.h>

#define B_   128
#define S_   512
#define IN_  128
#define H_   512
#define C_   1000
#define NWRP 16           // warps per rnn block
#define HSPW 36           // per-warp Hs row pitch (floats), 16B-aligned

// Scratch (device globals: allocation-free per harness rules)
__device__ float g_xp [(size_t)B_ * S_ * H_];           // input projection
__device__ float g_seq[(size_t)B_ * S_ * H_];           // layer-0 hidden sequence
__device__ unsigned long long g_h[2 * B_ * H_];         // (seq<<32|f32) h double-buffer
__device__ unsigned g_lbase[128];                       // per-block launch bases

// ---------------- packed fp32x2 helpers (SASS FFMA2 path) -------------------
__device__ __forceinline__ unsigned long long pack2(float lo, float hi) {
    unsigned long long d;
    asm("mov.b64 %0, {%1, %2};" : "=l"(d)
        : "r"(__float_as_uint(lo)), "r"(__float_as_uint(hi)));
    return d;
}
__device__ __forceinline__ unsigned long long ffma2(
    unsigned long long a, unsigned long long b, unsigned long long c) {
    unsigned long long d;
    asm("fma.rn.f32x2 %0, %1, %2, %3;" : "=l"(d) : "l"(a), "l"(b), "l"(c));
    return d;
}
__device__ __forceinline__ unsigned long long fadd2(
    unsigned long long a, unsigned long long b) {
    unsigned long long d;
    asm("add.rn.f32x2 %0, %1, %2;" : "=l"(d) : "l"(a), "l"(b));
    return d;
}
// STRONG relaxed 8B ops: guaranteed single-copy atomic (no tearing), L1-bypassing.
__device__ __forceinline__ unsigned long long ld_relaxed_u64(
    const unsigned long long* p) {
    unsigned long long r;
    asm volatile("ld.relaxed.gpu.global.b64 %0, [%1];"
                 : "=l"(r) : "l"(p) : "memory");
    return r;
}
__device__ __forceinline__ void st_relaxed_u64(unsigned long long* p,
                                               unsigned long long v) {
    asm volatile("st.relaxed.gpu.global.b64 [%0], %1;"
                 :: "l"(p), "l"(v) : "memory");
}

// ---------------------------------------------------------------------------
// Persistent RNN layer, seq-tagged h exchange (NO flags, NO fences).
// Grid (8,16) = 128 blocks, 512 threads (16 warps). Block tile: 16 rows
// (m0=bx*16) x 32 cols (n0=by*32). Whh tile [512][32] resident in smem.
// Each h element lives in gmem as u64 (seq<<32 | f32bits); the STRONG
// relaxed store of it is the release, the STRONG relaxed load is the
// acquire+detect (value and tag are one atomic word -> a matched tag proves
// the value). Warp g consumes k-slice [32g,32g+32) = output tile of block
// (bx, by=g): 16 coalesced 8B loads per lane (two batches of 8), retries
// stale ones, stages f32 into warp-private smem, runs the 4x4 f32x2
// microtile. Pr parity-double-buffered -> ONE __syncthreads per step.
// Buffer-reuse safety: h_t's stored value data-depends on ALL of the block's
// staged h_{t-1} words (via smem + barrier), so observing h_t proves its
// producer finished reading h_{t-1}; h_{t+1} (which overwrites h_{t-1}) is
// only stored after staging h_t from every producer of this row group.
// g_lbase[fi] += S_ at kernel end keeps seqs monotonic across launches and
// graph replays (all blocks' bases stay equal; seq never 0).
// ---------------------------------------------------------------------------
__global__ void __launch_bounds__(512, 1) rnn_layer_kernel(
    const float* __restrict__ xp, const float* __restrict__ Wh,
    float* __restrict__ seqOut)
{
    extern __shared__ float sm[];
    float* Ws  = sm;                       // [512][32] k-major        (64 KB)
    float* Hs  = Ws + 512 * 32;            // 16 x [16][HSPW] per-warp (36 KB)
    float* Pr0 = Hs + NWRP * 16 * HSPW;    // [16][512] partials buf 0 (32 KB)
    float* Pr1 = Pr0 + NWRP * 512;         // [16][512] partials buf 1 (32 KB)
    __shared__ unsigned s_base;

    const int tid  = threadIdx.x;
    const int bx   = blockIdx.x;
    const int by   = blockIdx.y;
    const int m0   = bx << 4;             // 8 m-groups  -> 128 rows
    const int n0   = by << 5;             // 16 n-groups -> 512 cols
    const int g    = tid >> 5;            // warp = K-group 0..15
    const int lane = tid & 31;
    const int r0   = (lane >> 3) << 2;    // rows r0..r0+3
    const int c0   = (lane & 7) << 2;     // cols c0..c0+3
    const int kbeg = g << 5;              // 32 k per warp
    const int fi   = (bx << 4) + by;      // own lbase index
    float* HsW = Hs + g * (16 * HSPW);

    unsigned long long* hAu = g_h;                 // buffer A (u64-tagged)
    unsigned long long* hBu = g_h + B_ * H_;       // buffer B

    if (tid == 0) s_base = g_lbase[fi];   // own counter: race-free

    // Load Whh tile once: Ws[k][n], n in [n0, n0+32), k in [0,512)
    for (int i = tid; i < 32 * 128; i += 512) {
        int n  = i & 31;
        int k4 = i >> 5;
        float4 v = *reinterpret_cast<const float4*>(
            &Wh[(size_t)(n0 + n) * H_ + (k4 << 2)]);
        int k = k4 << 2;
        Ws[(k + 0) * 32 + n] = v.x;
        Ws[(k + 1) * 32 + n] = v.y;
        Ws[(k + 2) * 32 + n] = v.z;
        Ws[(k + 3) * 32 + n] = v.w;
    }
    __syncthreads();
    const unsigned base = s_base;

    // Output ownership: thread tid -> row m0+(tid>>5), col n0+(tid&31)
    const int er = tid >> 5;              // == g
    const int ec = tid & 31;

    const float* xrow = xp + ((size_t)(m0 + er) * S_) * H_ + n0 + ec;
    float xv = __ldg(xrow);               // t = 0

    for (int t = 0; t < S_; ++t) {
        const unsigned long long* hpu = (t & 1) ? hAu : hBu;
        unsigned long long*       hnu = (t & 1) ? hBu : hAu;
        float*                    Pr  = (t & 1) ? Pr1 : Pr0;

        float s = 0.f;

        if (t > 0) {
            const unsigned expect = base + (unsigned)t;   // seq of h_{t-1}

            // Stage own k-slice: 16 rows x 32 k. One row per load slot
            // (lane = k-column -> coalesced 256B/row). Two batches of 8
            // parallel loads, then a retry pass per batch.
#pragma unroll
            for (int half = 0; half < 2; ++half) {
                unsigned long long v[8];
#pragma unroll
                for (int j = 0; j < 8; ++j) {
                    int r = (half << 3) + j;
                    v[j] = ld_relaxed_u64(
                        hpu + (size_t)(m0 + r) * H_ + kbeg + lane);
                }
#pragma unroll
                for (int j = 0; j < 8; ++j) {
                    int r = (half << 3) + j;
                    const unsigned long long* ap =
                        hpu + (size_t)(m0 + r) * H_ + kbeg + lane;
                    unsigned long long x = v[j];
                    while ((unsigned)(x >> 32) != expect)
                        x = ld_relaxed_u64(ap);
                    HsW[r * HSPW + lane] = __uint_as_float((unsigned)x);
                }
            }
            __syncwarp();

            unsigned long long a00 = 0, a01 = 0, a10 = 0, a11 = 0;
            unsigned long long a20 = 0, a21 = 0, a30 = 0, a31 = 0;

#pragma unroll
            for (int k4i = 0; k4i < 8; ++k4i) {
                const int kk = k4i << 2;
                float4 h0 = *reinterpret_cast<const float4*>(&HsW[(r0 + 0) * HSPW + kk]);
                float4 h1 = *reinterpret_cast<const float4*>(&HsW[(r0 + 1) * HSPW + kk]);
                float4 h2 = *reinterpret_cast<const float4*>(&HsW[(r0 + 2) * HSPW + kk]);
                float4 h3 = *reinterpret_cast<const float4*>(&HsW[(r0 + 3) * HSPW + kk]);
#define RNN_SUBK(ss, C)                                                        \
                {                                                              \
                    const ulonglong2 w = *reinterpret_cast<const ulonglong2*>( \
                        &Ws[(kbeg + kk + ss) * 32 + c0]);                      \
                    unsigned long long d;                                      \
                    d = pack2(h0.C, h0.C);                                     \
                    a00 = ffma2(d, w.x, a00); a01 = ffma2(d, w.y, a01);        \
                    d = pack2(h1.C, h1.C);                                     \
                    a10 = ffma2(d, w.x, a10); a11 = ffma2(d, w.y, a11);        \
                    d = pack2(h2.C, h2.C);                                     \
                    a20 = ffma2(d, w.x, a20); a21 = ffma2(d, w.y, a21);        \
                    d = pack2(h3.C, h3.C);                                     \
                    a30 = ffma2(d, w.x, a30); a31 = ffma2(d, w.y, a31);        \
                }
                RNN_SUBK(0, x)
                RNN_SUBK(1, y)
                RNN_SUBK(2, z)
                RNN_SUBK(3, w)
#undef RNN_SUBK
            }

            // Partials: Pr[g][row*32 + col]
            float* pg = &Pr[g << 9];
            *reinterpret_cast<ulonglong2*>(&pg[(r0 + 0) * 32 + c0]) = make_ulonglong2(a00, a01);
            *reinterpret_cast<ulonglong2*>(&pg[(r0 + 1) * 32 + c0]) = make_ulonglong2(a10, a11);
            *reinterpret_cast<ulonglong2*>(&pg[(r0 + 2) * 32 + c0]) = make_ulonglong2(a20, a21);
            *reinterpret_cast<ulonglong2*>(&pg[(r0 + 3) * 32 + c0]) = make_ulonglong2(a30, a31);
            __syncthreads();      // the ONLY block barrier per step

            // 16-way reduction: thread tid sums Pr[gg][tid]
#pragma unroll
            for (int gg = 0; gg < 16; ++gg)
                s += Pr[(gg << 9) + tid];
        }
        // t == 0: h_{-1}=0 -> output = tanh(xp)

        float o = tanhf(s + xv);
        // Tagged STRONG store IS the release (value+seq in one atomic word).
        unsigned long long pw =
            ((unsigned long long)(base + (unsigned)t + 1u) << 32) |
            (unsigned long long)__float_as_uint(o);
        st_relaxed_u64(&hnu[(size_t)(m0 + er) * H_ + n0 + ec], pw);

        if (seqOut)
            __stcg(&seqOut[((size_t)(m0 + er) * S_ + t) * H_ + n0 + ec], o);

        if (t != S_ - 1)   // prefetch next xp (hides under next stage/retry)
            xv = __ldg(xrow + (size_t)(t + 1) * H_);
    }

    if (tid == 0) g_lbase[fi] += (unsigned)S_;   // next launch's base
}

// ---------------------------------------------------------------------------
// C[M,N] = A[M,K] @ W[N,K]^T + b1[N] + b2[N]
// 128x64 tile, BK=16, 256 threads, 8x4 microtile, packed f32x2 FMAs,
// register double-buffering of the next K-tile to hide GMEM latency.
// ---------------------------------------------------------------------------
__global__ __launch_bounds__(256) void sgemm_bias(
    const float* __restrict__ A, const float* __restrict__ W,
    const float* __restrict__ b1, const float* __restrict__ b2,
    float* __restrict__ C, int M, int N, int K)
{
    __shared__ float As[16][132];
    __shared__ float Wt[16][68];
    const int tid = threadIdx.x;
    const int tx = tid & 15, ty = tid >> 4;
    const int m0 = blockIdx.x * 128, n0 = blockIdx.y * 64;

    const int a_lr = tid >> 2, a_lk = (tid & 3) << 2;
    const int w_ln = tid >> 2, w_lk = (tid & 3) << 2;
    const float* Ap0 = &A[(size_t)(m0 + a_lr) * K + a_lk];
    const float* Ap1 = &A[(size_t)(m0 + a_lr + 64) * K + a_lk];
    const float* Wp  = &W[(size_t)(n0 + w_ln) * K + w_lk];

    unsigned long long acc[8][2];
#pragma unroll
    for (int i = 0; i < 8; ++i) { acc[i][0] = 0; acc[i][1] = 0; }

    float4 av0 = *reinterpret_cast<const float4*>(Ap0);
    float4 av1 = *reinterpret_cast<const float4*>(Ap1);
    float4 wv  = *reinterpret_cast<const float4*>(Wp);

    for (int k0 = 0; k0 < K; k0 += 16) {
        As[a_lk + 0][a_lr] = av0.x; As[a_lk + 1][a_lr] = av0.y;
        As[a_lk + 2][a_lr] = av0.z; As[a_lk + 3][a_lr] = av0.w;
        As[a_lk + 0][a_lr + 64] = av1.x; As[a_lk + 1][a_lr + 64] = av1.y;
        As[a_lk + 2][a_lr + 64] = av1.z; As[a_lk + 3][a_lr + 64] = av1.w;
        Wt[w_lk + 0][w_ln] = wv.x; Wt[w_lk + 1][w_ln] = wv.y;
        Wt[w_lk + 2][w_ln] = wv.z; Wt[w_lk + 3][w_ln] = wv.w;
        __syncthreads();

        if (k0 + 16 < K) {
            av0 = *reinterpret_cast<const float4*>(Ap0 + k0 + 16);
            av1 = *reinterpret_cast<const float4*>(Ap1 + k0 + 16);
            wv  = *reinterpret_cast<const float4*>(Wp  + k0 + 16);
        }

#pragma unroll
        for (int kk = 0; kk < 16; ++kk) {
            float4 x0 = *reinterpret_cast<const float4*>(&As[kk][ty << 3]);
            float4 x1 = *reinterpret_cast<const float4*>(&As[kk][(ty << 3) + 4]);
            const ulonglong2 w = *reinterpret_cast<const ulonglong2*>(&Wt[kk][tx << 2]);
            unsigned long long d;
#define GEMM_ROW(i, av, C)                                                     \
            d = pack2(av.C, av.C);                                             \
            acc[i][0] = ffma2(d, w.x, acc[i][0]);                              \
            acc[i][1] = ffma2(d, w.y, acc[i][1]);
            GEMM_ROW(0, x0, x) GEMM_ROW(1, x0, y) GEMM_ROW(2, x0, z) GEMM_ROW(3, x0, w)
            GEMM_ROW(4, x1, x) GEMM_ROW(5, x1, y) GEMM_ROW(6, x1, z) GEMM_ROW(7, x1, w)
#undef GEMM_ROW
        }
        __syncthreads();
    }

    const int n = n0 + (tx << 2);
    unsigned long long bb0 = pack2(b1[n + 0] + b2[n + 0], b1[n + 1] + b2[n + 1]);
    unsigned long long bb1 = pack2(b1[n + 2] + b2[n + 2], b1[n + 3] + b2[n + 3]);
#pragma unroll
    for (int i = 0; i < 8; ++i) {
        int m = m0 + (ty << 3) + i;
        *reinterpret_cast<ulonglong2*>(&C[(size_t)m * N + n]) =
            make_ulonglong2(fadd2(acc[i][0], bb0), fadd2(acc[i][1], bb1));
    }
}

// ---------------------------------------------------------------------------
// logits = h_last @ W_out^T + b_out; out = log_softmax(logits)
// h_last comes from the tagged u64 buffer (low 32 bits = f32).
// ---------------------------------------------------------------------------
__global__ __launch_bounds__(256) void out_kernel(
    const unsigned long long* __restrict__ h, const float* __restrict__ Wout,
    const float* __restrict__ bout, float* __restrict__ out)
{
    __shared__ float hs[H_];
    __shared__ float logits[C_];
    __shared__ float red[8];
    int b = blockIdx.x;
    int tid = threadIdx.x;
    int warp = tid >> 5, lane = tid & 31;

    for (int k = tid; k < H_; k += 256)
        hs[k] = __uint_as_float((unsigned)h[(size_t)b * H_ + k]);
    __syncthreads();

    for (int c = warp; c < C_; c += 8) {
        const float* wr = Wout + (size_t)c * H_;
        float s = 0.f;
#pragma unroll
        for (int k = lane; k < H_; k += 32) s += hs[k] * wr[k];
#pragma unroll
        for (int off = 16; off > 0; off >>= 1) s += __shfl_down_sync(0xffffffffu, s, off);
        if (lane == 0) logits[c] = s + bout[c];
    }
    __syncthreads();

    float mx = -1e30f;
    for (int c = tid; c < C_; c += 256) mx = fmaxf(mx, logits[c]);
#pragma unroll
    for (int off = 16; off > 0; off >>= 1) mx = fmaxf(mx, __shfl_down_sync(0xffffffffu, mx, off));
    if (lane == 0) red[warp] = mx;
    __syncthreads();
    if (tid == 0) {
        float m2 = red[0];
        for (int i = 1; i < 8; i++) m2 = fmaxf(m2, red[i]);
        red[0] = m2;
    }
    __syncthreads();
    mx = red[0];
    __syncthreads();

    float se = 0.f;
    for (int c = tid; c < C_; c += 256) se += expf(logits[c] - mx);
#pragma unroll
    for (int off = 16; off > 0; off >>= 1) se += __shfl_down_sync(0xffffffffu, se, off);
    if (lane == 0) red[warp] = se;
    __syncthreads();
    if (tid == 0) {
        float s2 = 0.f;
        for (int i = 0; i < 8; i++) s2 += red[i];
        red[0] = logf(s2);
    }
    __syncthreads();
    float lse = red[0];

    for (int c = tid; c < C_; c += 256)
        out[(size_t)b * C_ + c] = logits[c] - mx - lse;
}

extern "C" void kernel_launch(void* const* d_in, const int* in_sizes, int n_in,
                              void* d_out, int out_size)
{
    (void)in_sizes; (void)n_in; (void)out_size;
    const float* x     = (const float*)d_in[0];
    const float* W_ih0 = (const float*)d_in[1];
    const float* W_hh0 = (const float*)d_in[2];
    const float* b_ih0 = (const float*)d_in[3];
    const float* b_hh0 = (const float*)d_in[4];
    const float* W_ih1 = (const float*)d_in[5];
    const float* W_hh1 = (const float*)d_in[6];
    const float* b_ih1 = (const float*)d_in[7];
    const float* b_hh1 = (const float*)d_in[8];
    const float* W_out = (const float*)d_in[9];
    const float* b_out = (const float*)d_in[10];
    float* out = (float*)d_out;

    float *xp, *seq;
    unsigned long long* hbuf;
    cudaGetSymbolAddress((void**)&xp,   g_xp);
    cudaGetSymbolAddress((void**)&seq,  g_seq);
    cudaGetSymbolAddress((void**)&hbuf, g_h);

    const int smem_bytes =
        (512 * 32 + NWRP * 16 * HSPW + 2 * NWRP * 512) * 4;  // 167936
    cudaFuncSetAttribute(rnn_layer_kernel,
                         cudaFuncAttributeMaxDynamicSharedMemorySize, smem_bytes);

    dim3 gg(B_ * S_ / 128, H_ / 64);  // (512, 8)
    dim3 gr(B_ / 16, H_ / 32);        // (8, 16) = 128 persistent blocks

    // layer 0
    sgemm_bias<<<gg, 256>>>(x, W_ih0, b_ih0, b_hh0, xp, B_ * S_, H_, IN_);
    rnn_layer_kernel<<<gr, 512, smem_bytes>>>(xp, W_hh0, seq);

    // layer 1
    sgemm_bias<<<gg, 256>>>(seq, W_ih1, b_ih1, b_hh1, xp, B_ * S_, H_, H_);
    rnn_layer_kernel<<<gr, 512, smem_bytes>>>(xp, W_hh1, nullptr);

    // output head on h_{S-1} (t=511 odd -> final state in buffer B)
    out_kernel<<<B_, 256>>>(hbuf + B_ * H_, W_out, b_out, out);
}